// round 15
// baseline (speedup 1.0000x reference)
#include <cuda_runtime.h>
#include <cuda_bf16.h>
#include <math.h>
#include <stdint.h>

#define N_ROWS 4096
#define D_DIM  1024
#define TWO_N  8192
#define INV_TEMP 20.0f
#define NEG_INF (-1e30f)

#define BM 128
#define BN 128
#define BK 64                    // bf16 elements per k-chunk (128 B rows)
#define NK (D_DIM / BK)          // 16 k-chunks
#define CT_TILES (TWO_N / BN)    // 64 column tiles
#define RB_TILES (N_ROWS / BM)   // 32 row tiles
#define NSTAGE 3
#define STAGE_BYTES (2 * 128 * 128)      // sA (16 KB) + sB (16 KB) per stage
#define SMEM_TOTAL (NSTAGE * STAGE_BYTES) // 96 KB dynamic

// Full-width XOR swizzle for 128B rows: row r (0..127), 16B chunk c (0..7).
// chunk' = c ^ (r & 7): conflict-free for cp.async 16B stores and every
// ldmatrix phase.
#define SWOFF128(r, c) (((uint32_t)(r) << 7) | ((((c) ^ ((r) & 7))) << 4))

// -------------------------- scratch (no allocs) ----------------------------
__device__ __nv_bfloat16 g_Xn[(size_t)N_ROWS * D_DIM];   // 8 MB
__device__ __nv_bfloat16 g_Bn[(size_t)TWO_N * D_DIM];    // 16 MB (tgt ; neg)
__device__ float g_diag[N_ROWS];
// ct-major partials: g_pm[ct * N_ROWS + row]  (1 MB each)
__device__ float g_pm[(size_t)CT_TILES * N_ROWS];
__device__ float g_ps[(size_t)CT_TILES * N_ROWS];
__device__ float g_bsum[16];
__device__ unsigned int g_count;   // zero-initialized; reset by last block

// -------------------------- PTX helpers ------------------------------------
__device__ __forceinline__ uint32_t smem_u32(const void* p) {
    uint32_t a;
    asm("{ .reg .u64 t; cvta.to.shared.u64 t, %1; cvt.u32.u64 %0, t; }" : "=r"(a) : "l"(p));
    return a;
}

#define CP_ASYNC16(saddr, gptr) \
    asm volatile("cp.async.cg.shared.global [%0], [%1], 16;" :: "r"(saddr), "l"(gptr))
#define CP_COMMIT() asm volatile("cp.async.commit_group;" ::: "memory")
#define CP_WAIT1()  asm volatile("cp.async.wait_group 1;" ::: "memory")

#define LDSM_X4(r, a) \
    asm volatile("ldmatrix.sync.aligned.m8n8.x4.shared.b16 {%0,%1,%2,%3}, [%4];" \
        : "=r"((r)[0]), "=r"((r)[1]), "=r"((r)[2]), "=r"((r)[3]) : "r"(a))

#define MMA16816(d, a0, a1, a2, a3, b0, b1) \
    asm volatile("mma.sync.aligned.m16n8k16.row.col.f32.bf16.bf16.f32 " \
        "{%0,%1,%2,%3}, {%4,%5,%6,%7}, {%8,%9}, {%0,%1,%2,%3};" \
        : "+f"((d)[0]), "+f"((d)[1]), "+f"((d)[2]), "+f"((d)[3]) \
        : "r"(a0), "r"(a1), "r"(a2), "r"(a3), "r"(b0), "r"(b1))

// ---------------------------------------------------------------------------
// Kernel 1: row-normalize -> bf16, warp-per-row, TWO-PASS (low regs -> high
// occupancy -> more loads in flight). Pass 1: sum of squares (values
// discarded). Pass 2: re-read (L2-hit), scale, convert, store.
// target -> g_Bn[0:N), hard_neg -> g_Bn[N:2N)
// ---------------------------------------------------------------------------
__global__ __launch_bounds__(256) void normalize_kernel(
    const float* __restrict__ inp,
    const float* __restrict__ tgt,
    const float* __restrict__ neg)
{
    const int wid  = threadIdx.x >> 5;
    const int lane = threadIdx.x & 31;
    const int row  = blockIdx.x * 8 + wid;     // 0..12287

    const float* src;
    __nv_bfloat16* dst;
    if (row < N_ROWS) {
        src = inp + (size_t)row * D_DIM;
        dst = g_Xn + (size_t)row * D_DIM;
    } else if (row < 2 * N_ROWS) {
        int r = row - N_ROWS;
        src = tgt + (size_t)r * D_DIM;
        dst = g_Bn + (size_t)r * D_DIM;
    } else {
        int r = row - 2 * N_ROWS;
        src = neg + (size_t)r * D_DIM;
        dst = g_Bn + (size_t)(N_ROWS + r) * D_DIM;
    }

    // Pass 1: sum of squares, values not kept live.
    float ss = 0.f;
    #pragma unroll
    for (int i = 0; i < 8; i++) {
        const float4 v = ((const float4*)src)[lane + 32 * i];
        ss += v.x * v.x + v.y * v.y + v.z * v.z + v.w * v.w;
    }
    #pragma unroll
    for (int o = 16; o; o >>= 1) ss += __shfl_xor_sync(0xffffffffu, ss, o);
    const float inv = 1.0f / fmaxf(sqrtf(ss), 1e-8f);

    // Pass 2: re-read (row resides in L2), scale, convert, store.
    #pragma unroll
    for (int i = 0; i < 8; i++) {
        const float4 v = ((const float4*)src)[lane + 32 * i];
        __nv_bfloat162 h0 = __floats2bfloat162_rn(v.x * inv, v.y * inv);
        __nv_bfloat162 h1 = __floats2bfloat162_rn(v.z * inv, v.w * inv);
        uint2 packed;
        packed.x = *(uint32_t*)&h0;
        packed.y = *(uint32_t*)&h1;
        ((uint2*)dst)[lane + 32 * i] = packed;
    }
}

// ---------------------------------------------------------------------------
// Kernel 2: bf16 HMMA GEMM (mma.sync m16n8k16) + fused online logsumexp.
// 128x128 tile per CTA, 8 warps (2x4), BK=64, 3-stage cp.async pipeline in
// 96 KB dynamic smem (2 CTAs/SM), XOR-swizzled 128B rows. B fragments
// pair-loaded via ldmatrix.x4. (FROZEN — R9/R12 winner.)
// ---------------------------------------------------------------------------
__global__ __launch_bounds__(256, 2) void sim_lse_mma()
{
    extern __shared__ __align__(1024) uint8_t smem_dyn[];

    const int tid    = threadIdx.x;
    const int wid    = tid >> 5;
    const int lane   = tid & 31;
    const int warp_m = wid >> 2;        // 0..1
    const int warp_n = wid & 3;         // 0..3
    const int ct     = blockIdx.x;      // 0..63
    const int rb     = blockIdx.y;      // 0..31
    const int row0   = rb * BM;
    const int col0   = ct * BN;

    const uint32_t sbase = smem_u32(smem_dyn);

    // cp.async: 4 segments per matrix per chunk per thread.
    uint32_t doff[4];
    const __nv_bfloat16* gA[4];
    const __nv_bfloat16* gB[4];
    #pragma unroll
    for (int i = 0; i < 4; i++) {
        const int seg = tid + i * 256;
        const int r = seg >> 3;
        const int c = seg & 7;
        doff[i] = SWOFF128(r, c);
        gA[i] = &g_Xn[(size_t)(row0 + r) * D_DIM + c * 8];
        gB[i] = &g_Bn[(size_t)(col0 + r) * D_DIM + c * 8];
    }

    // ldmatrix bases. xr = row&7 (= lane&7 for all fragment rows here).
    const uint32_t xr   = lane & 7;
    const uint32_t a_cb = lane >> 4;          // A: 16-lane halves
    const uint32_t b_cb = (lane >> 3) & 1;    // B: k-half select
    uint32_t a_rowb[4], b_rowb[2];
    #pragma unroll
    for (int mt = 0; mt < 4; mt++) {
        const int r = warp_m * 64 + mt * 16 + (lane & 15);
        a_rowb[mt] = (uint32_t)r << 7;
    }
    #pragma unroll
    for (int jp = 0; jp < 2; jp++) {          // nt pair jp -> nt {2jp, 2jp+1}
        const int r = warp_n * 32 + jp * 16 + ((lane >> 1) & 8) + (lane & 7);
        b_rowb[jp] = (uint32_t)r << 7;
    }

    float acc[4][4][4];
    #pragma unroll
    for (int mt = 0; mt < 4; mt++)
        #pragma unroll
        for (int nt = 0; nt < 4; nt++)
            #pragma unroll
            for (int q = 0; q < 4; q++) acc[mt][nt][q] = 0.f;

    // prologue: stages 0 and 1
    #pragma unroll
    for (int p = 0; p < 2; p++) {
        const int k0 = p * BK;
        const uint32_t dA = sbase + p * STAGE_BYTES;
        const uint32_t dB = dA + 128 * 128;
        #pragma unroll
        for (int i = 0; i < 4; i++) {
            CP_ASYNC16(dA + doff[i], gA[i] + k0);
            CP_ASYNC16(dB + doff[i], gB[i] + k0);
        }
        CP_COMMIT();
    }

    int stage = 0;
    for (int kc = 0; kc < NK; kc++) {
        CP_WAIT1();
        __syncthreads();

        if (kc + 2 < NK) {
            const int ps = (stage + 2 >= NSTAGE) ? stage + 2 - NSTAGE : stage + 2;
            const int k0 = (kc + 2) * BK;
            const uint32_t dA = sbase + ps * STAGE_BYTES;
            const uint32_t dB = dA + 128 * 128;
            #pragma unroll
            for (int i = 0; i < 4; i++) {
                CP_ASYNC16(dA + doff[i], gA[i] + k0);
                CP_ASYNC16(dB + doff[i], gB[i] + k0);
            }
        }
        CP_COMMIT();

        const uint32_t baseA = sbase + stage * STAGE_BYTES;
        const uint32_t baseB = baseA + 128 * 128;
        #pragma unroll
        for (int ks = 0; ks < 4; ks++) {
            uint32_t af[4][4], bf[2][4];
            #pragma unroll
            for (int mt = 0; mt < 4; mt++) {
                const uint32_t chunk = (2u * ks + a_cb) ^ xr;
                LDSM_X4(af[mt], baseA + (a_rowb[mt] | (chunk << 4)));
            }
            #pragma unroll
            for (int jp = 0; jp < 2; jp++) {
                const uint32_t chunk = (2u * ks + b_cb) ^ xr;
                LDSM_X4(bf[jp], baseB + (b_rowb[jp] | (chunk << 4)));
            }
            #pragma unroll
            for (int mt = 0; mt < 4; mt++)
                #pragma unroll
                for (int jp = 0; jp < 2; jp++) {
                    MMA16816(acc[mt][2 * jp],
                             af[mt][0], af[mt][1], af[mt][2], af[mt][3],
                             bf[jp][0], bf[jp][1]);
                    MMA16816(acc[mt][2 * jp + 1],
                             af[mt][0], af[mt][1], af[mt][2], af[mt][3],
                             bf[jp][2], bf[jp][3]);
                }
        }
        stage = (stage + 1 >= NSTAGE) ? 0 : stage + 1;
    }

    // ---- Epilogue ----
    __syncthreads();                           // all ldmatrix done; reuse smem
    float* sm_m = (float*)smem_dyn;            // [4][128]
    float* sm_s = (float*)smem_dyn + 4 * 128;  // [4][128]

    #pragma unroll
    for (int mt = 0; mt < 4; mt++) {
        #pragma unroll
        for (int h = 0; h < 2; h++) {
            const int rloc = warp_m * 64 + mt * 16 + (lane >> 2) + h * 8;
            const int gr = row0 + rloc;
            float v[8];
            float m = NEG_INF;
            #pragma unroll
            for (int nt = 0; nt < 4; nt++) {
                #pragma unroll
                for (int j = 0; j < 2; j++) {
                    float x = acc[mt][nt][h * 2 + j] * INV_TEMP;
                    const int gc = col0 + warp_n * 32 + nt * 8 + (lane & 3) * 2 + j;
                    if (gc == gr) g_diag[gr] = x;           // pos_sim diagonal
                    if (gc == N_ROWS + gr) x += 1.0f;       // hard-negative weight
                    v[nt * 2 + j] = x;
                    m = fmaxf(m, x);
                }
            }
            float s = 0.f;
            #pragma unroll
            for (int j = 0; j < 8; j++) s += __expf(v[j] - m);
            // combine across the 4 lanes of the quad (same row)
            #pragma unroll
            for (int off = 1; off <= 2; off <<= 1) {
                float om = __shfl_xor_sync(0xffffffffu, m, off);
                float os = __shfl_xor_sync(0xffffffffu, s, off);
                float mn = fmaxf(m, om);
                s = s * __expf(m - mn) + os * __expf(om - mn);
                m = mn;
            }
            if ((lane & 3) == 0) {
                sm_m[warp_n * 128 + rloc] = m;
                sm_s[warp_n * 128 + rloc] = s;
            }
        }
    }
    __syncthreads();

    // threads 0..127: combine 4 warp_n partials for one row; coalesced store.
    if (tid < 128) {
        float m = sm_m[tid];
        float s = sm_s[tid];
        #pragma unroll
        for (int j = 1; j < 4; j++) {
            float om = sm_m[j * 128 + tid];
            float os = sm_s[j * 128 + tid];
            float mn = fmaxf(m, om);
            s = s * __expf(m - mn) + os * __expf(om - mn);
            m = mn;
        }
        const size_t p = (size_t)ct * N_ROWS + row0 + tid;
        g_pm[p] = m;
        g_ps[p] = s;
    }
}

// ---------------------------------------------------------------------------
// Kernel 3: per-row combine of 64 ct-major partials -> lse - diag; block sum;
// last block (atomic counter) sums the 16 block partials -> out. Deterministic
// (fixed-order sum of fixed 16 values).
// ---------------------------------------------------------------------------
__global__ __launch_bounds__(256) void rowloss_kernel(float* __restrict__ out)
{
    const int tid = threadIdx.x;
    const int r = blockIdx.x * 256 + tid;

    float m = NEG_INF;
    #pragma unroll 8
    for (int c = 0; c < CT_TILES; c++)
        m = fmaxf(m, g_pm[(size_t)c * N_ROWS + r]);
    float s = 0.f;
    #pragma unroll 8
    for (int c = 0; c < CT_TILES; c++)
        s += g_ps[(size_t)c * N_ROWS + r] * __expf(g_pm[(size_t)c * N_ROWS + r] - m);
    float local = (m + logf(s)) - g_diag[r];

    #pragma unroll
    for (int o = 16; o; o >>= 1) local += __shfl_xor_sync(0xffffffffu, local, o);
    __shared__ float warp_sum[8];
    const int w = tid >> 5, l = tid & 31;
    if (l == 0) warp_sum[w] = local;
    __syncthreads();
    if (tid == 0) {
        float t = 0.f;
        #pragma unroll
        for (int i = 0; i < 8; i++) t += warp_sum[i];
        g_bsum[blockIdx.x] = t;
        __threadfence();
        const unsigned int old = atomicAdd(&g_count, 1u);
        if (old == gridDim.x - 1) {          // last block finishes the mean
            __threadfence();
            float tot = 0.f;
            #pragma unroll
            for (int i = 0; i < 16; i++) tot += g_bsum[i];
            out[0] = tot / (float)N_ROWS;
            g_count = 0;                     // reset for next replay
        }
    }
}

// ---------------------------------------------------------------------------
extern "C" void kernel_launch(void* const* d_in, const int* in_sizes, int n_in,
                              void* d_out, int out_size)
{
    const float* inp = (const float*)d_in[0];
    const float* tgt = (const float*)d_in[1];
    const float* neg = (const float*)d_in[2];
    float* out = (float*)d_out;

    cudaFuncSetAttribute(sim_lse_mma,
                         cudaFuncAttributeMaxDynamicSharedMemorySize, SMEM_TOTAL);

    normalize_kernel<<<(3 * N_ROWS) / 8, 256>>>(inp, tgt, neg);

    dim3 grid(CT_TILES, RB_TILES);   // 64 x 32 = 2048 CTAs
    sim_lse_mma<<<grid, 256, SMEM_TOTAL>>>();

    rowloss_kernel<<<N_ROWS / 256, 256>>>(out);
}